// round 2
// baseline (speedup 1.0000x reference)
#include <cuda_runtime.h>
#include <cuda_bf16.h>

#define NBLOCKS 2048
#define NTHREADS 256

// Fixed partial-sum slots: every launched block writes its own slot
// unconditionally, so no zero-init pass is needed. No atomics -> deterministic.
__device__ float g_pos[NBLOCKS];
__device__ float g_neg[NBLOCKS];
__device__ int   g_cnt[NBLOCKS];

__device__ __forceinline__ float softplus_fast(float x) {
    // softplus(x) = max(x,0) + log(1 + exp(-|x|)); arg of log in [1,2] -> well conditioned
    float a = fabsf(x);
    return fmaxf(x, 0.0f) + __logf(1.0f + __expf(-a));
}

__device__ __forceinline__ void accum4(float4 x, int4 t,
                                       float& ps, float& ns, int& pc) {
    {
        float sp = softplus_fast(x.x);
        if (t.x == 1) { ps += sp - x.x; pc++; } else { ns += sp; }
    }
    {
        float sp = softplus_fast(x.y);
        if (t.y == 1) { ps += sp - x.y; pc++; } else { ns += sp; }
    }
    {
        float sp = softplus_fast(x.z);
        if (t.z == 1) { ps += sp - x.z; pc++; } else { ns += sp; }
    }
    {
        float sp = softplus_fast(x.w);
        if (t.w == 1) { ps += sp - x.w; pc++; } else { ns += sp; }
    }
}

__global__ void __launch_bounds__(NTHREADS)
loss_main(const float* __restrict__ pred, const int* __restrict__ truey, long long n4) {
    float ps = 0.0f, ns = 0.0f;
    int   pc = 0;

    const float4* __restrict__ p4 = (const float4*)pred;
    const int4*  __restrict__  t4 = (const int4*)truey;

    long long idx    = (long long)blockIdx.x * blockDim.x + threadIdx.x;
    long long stride = (long long)gridDim.x * blockDim.x;

    // Main loop: 2 grid-stride steps per iteration, loads front-batched so the
    // four 16B LDGs are all in flight before any math consumes them (MLP >= 4).
    long long i = idx;
    for (; i + stride < n4; i += 2 * stride) {
        float4 x0 = p4[i];
        int4   t0 = t4[i];
        float4 x1 = p4[i + stride];
        int4   t1 = t4[i + stride];
        accum4(x0, t0, ps, ns, pc);
        accum4(x1, t1, ps, ns, pc);
    }
    if (i < n4) {
        float4 x0 = p4[i];
        int4   t0 = t4[i];
        accum4(x0, t0, ps, ns, pc);
    }

    // Block tree reduction (deterministic)
    __shared__ float sps[NTHREADS];
    __shared__ float sns[NTHREADS];
    __shared__ int   spc[NTHREADS];
    int tid = threadIdx.x;
    sps[tid] = ps; sns[tid] = ns; spc[tid] = pc;
    __syncthreads();

#pragma unroll
    for (int off = NTHREADS / 2; off > 0; off >>= 1) {
        if (tid < off) {
            sps[tid] += sps[tid + off];
            sns[tid] += sns[tid + off];
            spc[tid] += spc[tid + off];
        }
        __syncthreads();
    }

    if (tid == 0) {
        g_pos[blockIdx.x] = sps[0];
        g_neg[blockIdx.x] = sns[0];
        g_cnt[blockIdx.x] = spc[0];
    }
}

__global__ void __launch_bounds__(1024)
loss_final(float* __restrict__ out, long long ntotal) {
    __shared__ float sps[1024];
    __shared__ float sns[1024];
    __shared__ int   spc[1024];

    int tid = threadIdx.x;
    float ps = 0.0f, ns = 0.0f;
    int pc = 0;
#pragma unroll
    for (int i = tid; i < NBLOCKS; i += 1024) {
        ps += g_pos[i];
        ns += g_neg[i];
        pc += g_cnt[i];
    }
    sps[tid] = ps; sns[tid] = ns; spc[tid] = pc;
    __syncthreads();

#pragma unroll
    for (int off = 512; off > 0; off >>= 1) {
        if (tid < off) {
            sps[tid] += sps[tid + off];
            sns[tid] += sns[tid + off];
            spc[tid] += spc[tid + off];
        }
        __syncthreads();
    }

    if (tid == 0) {
        float npos = (float)spc[0];
        float nneg = (float)(ntotal - (long long)spc[0]);
        out[0] = sps[0] / npos + sns[0] / nneg;
    }
}

extern "C" void kernel_launch(void* const* d_in, const int* in_sizes, int n_in,
                              void* d_out, int out_size) {
    const float* pred = (const float*)d_in[0];
    const int*   truey = (const int*)d_in[1];
    float* out = (float*)d_out;

    long long n = (long long)in_sizes[0];  // 8192*8192, divisible by 4
    long long n4 = n >> 2;

    loss_main<<<NBLOCKS, NTHREADS>>>(pred, truey, n4);
    loss_final<<<1, 1024>>>(out, n);
}

// round 3
// speedup vs baseline: 1.0215x; 1.0215x over previous
#include <cuda_runtime.h>
#include <cuda_bf16.h>

#define NBLOCKS 2048
#define NTHREADS 256

// Fixed partial-sum slots: every block writes its own slot unconditionally.
// No float atomics anywhere -> bitwise deterministic.
__device__ float g_pos[NBLOCKS];
__device__ float g_neg[NBLOCKS];
__device__ int   g_cnt[NBLOCKS];
__device__ unsigned int g_ticket = 0;  // self-resetting; last block zeroes it

__device__ __forceinline__ float softplus_fast(float x) {
    // softplus(x) = max(x,0) + log(1 + exp(-|x|)); log arg in [1,2] -> well conditioned
    float a = fabsf(x);
    return fmaxf(x, 0.0f) + __logf(1.0f + __expf(-a));
}

__device__ __forceinline__ void accum4(float4 x, int4 t,
                                       float& ps, float& ns, int& pc) {
    {
        float sp = softplus_fast(x.x);
        if (t.x == 1) { ps += sp - x.x; pc++; } else { ns += sp; }
    }
    {
        float sp = softplus_fast(x.y);
        if (t.y == 1) { ps += sp - x.y; pc++; } else { ns += sp; }
    }
    {
        float sp = softplus_fast(x.z);
        if (t.z == 1) { ps += sp - x.z; pc++; } else { ns += sp; }
    }
    {
        float sp = softplus_fast(x.w);
        if (t.w == 1) { ps += sp - x.w; pc++; } else { ns += sp; }
    }
}

__global__ void __launch_bounds__(NTHREADS)
loss_fused(const float* __restrict__ pred, const int* __restrict__ truey,
           float* __restrict__ out, long long n4, long long ntotal) {
    float ps = 0.0f, ns = 0.0f;
    int   pc = 0;

    const float4* __restrict__ p4 = (const float4*)pred;
    const int4*  __restrict__  t4 = (const int4*)truey;

    long long idx    = (long long)blockIdx.x * blockDim.x + threadIdx.x;
    long long stride = (long long)gridDim.x * blockDim.x;

    // 4 grid-stride steps per iteration; all 8 streaming LDG.128s issued
    // before any math consumes them (MLP >= 8 per thread).
    long long i = idx;
    for (; i + 3 * stride < n4; i += 4 * stride) {
        float4 x0 = __ldcs(p4 + i);
        int4   t0 = __ldcs(t4 + i);
        float4 x1 = __ldcs(p4 + i + stride);
        int4   t1 = __ldcs(t4 + i + stride);
        float4 x2 = __ldcs(p4 + i + 2 * stride);
        int4   t2 = __ldcs(t4 + i + 2 * stride);
        float4 x3 = __ldcs(p4 + i + 3 * stride);
        int4   t3 = __ldcs(t4 + i + 3 * stride);
        accum4(x0, t0, ps, ns, pc);
        accum4(x1, t1, ps, ns, pc);
        accum4(x2, t2, ps, ns, pc);
        accum4(x3, t3, ps, ns, pc);
    }
    for (; i < n4; i += stride) {  // never taken for n4 = 2^24, kept for safety
        accum4(__ldcs(p4 + i), __ldcs(t4 + i), ps, ns, pc);
    }

    // Deterministic block tree reduction
    __shared__ float sps[NTHREADS];
    __shared__ float sns[NTHREADS];
    __shared__ int   spc[NTHREADS];
    int tid = threadIdx.x;
    sps[tid] = ps; sns[tid] = ns; spc[tid] = pc;
    __syncthreads();

#pragma unroll
    for (int off = NTHREADS / 2; off > 0; off >>= 1) {
        if (tid < off) {
            sps[tid] += sps[tid + off];
            sns[tid] += sns[tid + off];
            spc[tid] += spc[tid + off];
        }
        __syncthreads();
    }

    __shared__ unsigned int s_is_last;
    if (tid == 0) {
        g_pos[blockIdx.x] = sps[0];
        g_neg[blockIdx.x] = sns[0];
        g_cnt[blockIdx.x] = spc[0];
        __threadfence();  // make partials visible before taking a ticket
        unsigned int ticket = atomicAdd(&g_ticket, 1u);
        s_is_last = (ticket == (unsigned int)(NBLOCKS - 1)) ? 1u : 0u;
    }
    __syncthreads();

    if (s_is_last) {
        // Last block: reduce all fixed slots in fixed order (deterministic).
        float fps = 0.0f, fns = 0.0f;
        int   fpc = 0;
#pragma unroll
        for (int k = tid; k < NBLOCKS; k += NTHREADS) {  // 8 slots each, fixed order
            fps += g_pos[k];
            fns += g_neg[k];
            fpc += g_cnt[k];
        }
        sps[tid] = fps; sns[tid] = fns; spc[tid] = fpc;
        __syncthreads();
#pragma unroll
        for (int off = NTHREADS / 2; off > 0; off >>= 1) {
            if (tid < off) {
                sps[tid] += sps[tid + off];
                sns[tid] += sns[tid + off];
                spc[tid] += spc[tid + off];
            }
            __syncthreads();
        }
        if (tid == 0) {
            float npos = (float)spc[0];
            float nneg = (float)(ntotal - (long long)spc[0]);
            out[0] = sps[0] / npos + sns[0] / nneg;
            g_ticket = 0;  // reset for next graph replay
        }
    }
}

extern "C" void kernel_launch(void* const* d_in, const int* in_sizes, int n_in,
                              void* d_out, int out_size) {
    const float* pred  = (const float*)d_in[0];
    const int*   truey = (const int*)d_in[1];
    float* out = (float*)d_out;

    long long n  = (long long)in_sizes[0];  // 8192*8192, divisible by 4
    long long n4 = n >> 2;

    loss_fused<<<NBLOCKS, NTHREADS>>>(pred, truey, out, n4, n);
}